// round 4
// baseline (speedup 1.0000x reference)
#include <cuda_runtime.h>

// DimeNetPP radius-graph distances + triplet angles.
// Inputs: [0] atomic_ns (unused), [1] coords f32 [N,3], [2] batch_node_vec (unused)
// Output: f32, dists [B,48,48] then angles [B,48,48,48].

#define MOL_B 128
#define MM 48
#define SPLIT 4
#define JS (MM / SPLIT)          // 12 center rows (j) per CTA
#define THREADS 256
#define NWARP (THREADS / 32)
#define CUTOFF_F 1.5f

// Branch-free atan2 for y >= 0, (x,y) != (0,0). Max rel err ~1.3e-4.
__device__ __forceinline__ float fast_atan2_pos(float y, float x)
{
    const float ax = fabsf(x);
    const float mn = fminf(y, ax);
    const float mx = fmaxf(y, ax);
    const float t  = __fdividef(mn, mx);
    const float s  = t * t;
    float p = fmaf(s, 0.0208351f, -0.0851330f);
    p = fmaf(s, p, 0.1801410f);
    p = fmaf(s, p, -0.3302995f);
    p = fmaf(s, p, 0.9998660f);
    p = p * t;
    p = (y > ax) ? (1.57079632679f - p) : p;
    p = (x < 0.0f) ? (3.14159265359f - p) : p;
    return p;
}

__global__ __launch_bounds__(THREADS)
void dimenet_kernel(const float* __restrict__ coords, float* __restrict__ out)
{
    const int cta   = blockIdx.x;
    const int b     = cta >> 2;
    const int split = cta & 3;
    const int j0    = split * JS;
    const int tid   = threadIdx.x;
    const int wid   = tid >> 5;
    const int lane  = tid & 31;

    __shared__ float cs[MM * 3];
    __shared__ float d2row[JS][MM];
    __shared__ int   nbrs[JS][MM];
    __shared__ int   cnt[JS];

    if (tid < MM * 3) cs[tid] = coords[b * (MM * 3) + tid];
    __syncthreads();

    float* __restrict__ dists  = out;
    float* __restrict__ angles = out + (size_t)MOL_B * MM * MM;

    // Phase 1: per-row distances + ballot-compacted neighbor lists.
    // Warp w handles rows w, w+NWARP, ... Lanes cover q in two 32/16 chunks.
    for (int r = wid; r < JS; r += NWARP) {
        const int p  = j0 + r;
        const float px = cs[p * 3 + 0], py = cs[p * 3 + 1], pz = cs[p * 3 + 2];

        // chunk 0: q = lane (0..31)
        const int q0 = lane;
        float dx = px - cs[q0 * 3 + 0];
        float dy = py - cs[q0 * 3 + 1];
        float dz = pz - cs[q0 * 3 + 2];
        float d2 = dx * dx + dy * dy + dz * dz;
        d2row[r][q0] = d2;
        float dist = sqrtf(d2);
        bool adj0 = (q0 != p) && (dist < CUTOFF_F);
        dists[((size_t)b * MM + p) * MM + q0] = adj0 ? dist : 0.0f;
        const unsigned m0 = __ballot_sync(0xffffffffu, adj0);

        // chunk 1: q = lane + 32 (lanes 0..15 only)
        bool adj1 = false;
        const int q1 = lane + 32;
        if (lane < 16) {
            dx = px - cs[q1 * 3 + 0];
            dy = py - cs[q1 * 3 + 1];
            dz = pz - cs[q1 * 3 + 2];
            d2 = dx * dx + dy * dy + dz * dz;
            d2row[r][q1] = d2;
            dist = sqrtf(d2);
            adj1 = (q1 != p) && (dist < CUTOFF_F);
            dists[((size_t)b * MM + p) * MM + q1] = adj1 ? dist : 0.0f;
        }
        const unsigned m1 = __ballot_sync(0xffffffffu, adj1);

        const int c0 = __popc(m0);
        const unsigned below = (1u << lane) - 1u;
        if (adj0) nbrs[r][__popc(m0 & below)] = q0;
        if (adj1) nbrs[r][c0 + __popc(m1 & below)] = q1;
        if (lane == 0) cnt[r] = c0 + __popc(m1);
    }

    // Zero-fill this CTA's contiguous angle slab (independent of phase 1).
    {
        float4* zb = reinterpret_cast<float4*>(
            angles + (((size_t)b * MM + j0) * MM) * MM);
        const float4 z = make_float4(0.f, 0.f, 0.f, 0.f);
        #pragma unroll 8
        for (int e = tid; e < JS * MM * MM / 4; e += THREADS) zb[e] = z;
    }
    __syncthreads();

    // Per-thread prefix over cnt[] (LDS broadcasts; no extra barrier).
    int off[JS + 1];
    off[0] = 0;
    #pragma unroll
    for (int r = 0; r < JS; r++) {
        const int c = cnt[r];
        off[r + 1] = off[r] + c * c;
    }
    const int total = off[JS];

    // Phase 3: compute + scatter only the real triplets.
    #pragma unroll 4
    for (int g = tid; g < total; g += THREADS) {
        int jl = 0;
        #pragma unroll
        for (int r = 1; r < JS; r++) if (g >= off[r]) jl = r;
        const int p  = g - off[jl];
        const int c  = cnt[jl];
        const int pi = (int)__fdividef((float)p + 0.5f, (float)c);
        const int ii = nbrs[jl][pi];
        const int kk = nbrs[jl][p - pi * c];

        const int jg = j0 + jl;
        const float jx = cs[jg * 3 + 0];
        const float jy = cs[jg * 3 + 1];
        const float jz = cs[jg * 3 + 2];
        const float vix = cs[ii * 3 + 0] - jx;
        const float viy = cs[ii * 3 + 1] - jy;
        const float viz = cs[ii * 3 + 2] - jz;
        const float vkx = cs[kk * 3 + 0] - jx;
        const float vky = cs[kk * 3 + 1] - jy;
        const float vkz = cs[kk * 3 + 2] - jz;
        const float a  = vix * vkx + viy * vky + viz * vkz;
        const float b2 = fmaxf(d2row[jl][ii] * d2row[jl][kk] - a * a, 0.f);
        const float ang = fast_atan2_pos(sqrtf(b2), a);
        if (ii != kk)
            angles[(((size_t)b * MM + jg) * MM + ii) * MM + kk] = ang;
    }
}

extern "C" void kernel_launch(void* const* d_in, const int* in_sizes, int n_in,
                              void* d_out, int out_size)
{
    const float* coords = (const float*)d_in[1];
    float* out = (float*)d_out;
    dimenet_kernel<<<MOL_B * SPLIT, THREADS>>>(coords, out);
}

// round 6
// speedup vs baseline: 1.2096x; 1.2096x over previous
#include <cuda_runtime.h>

// DimeNetPP radius-graph distances + triplet angles.
// Inputs: [0] atomic_ns (unused), [1] coords f32 [N,3], [2] batch_node_vec (unused)
// Output: f32, dists [B,48,48] then angles [B,48,48,48].

#define MOL_B 128
#define MM 48
#define SPLIT 16
#define JS (MM / SPLIT)          // 3 center rows (j) per CTA
#define THREADS 128
#define CUTOFF_F 1.5f

// Branch-free atan2 for y >= 0, (x,y) != (0,0). Max rel err ~1.3e-4.
__device__ __forceinline__ float fast_atan2_pos(float y, float x)
{
    const float ax = fabsf(x);
    const float mn = fminf(y, ax);
    const float mx = fmaxf(y, ax);
    const float t  = __fdividef(mn, mx);
    const float s  = t * t;
    float p = fmaf(s, 0.0208351f, -0.0851330f);
    p = fmaf(s, p, 0.1801410f);
    p = fmaf(s, p, -0.3302995f);
    p = fmaf(s, p, 0.9998660f);
    p = p * t;
    p = (y > ax) ? (1.57079632679f - p) : p;
    p = (x < 0.0f) ? (3.14159265359f - p) : p;
    return p;
}

__global__ __launch_bounds__(THREADS)
void dimenet_kernel(const float* __restrict__ coords, float* __restrict__ out)
{
    const int cta   = blockIdx.x;
    const int b     = cta >> 4;
    const int split = cta & 15;
    const int j0    = split * JS;
    const int tid   = threadIdx.x;
    const int wid   = tid >> 5;
    const int lane  = tid & 31;

    __shared__ float cs[MM * 3];
    __shared__ float nx[JS][MM], ny[JS][MM], nz[JS][MM], nd2[JS][MM];
    __shared__ int   nk[JS][MM];
    __shared__ int   cnt[JS];

    // NOTE: MM*3 = 144 > THREADS, must loop.
    for (int e = tid; e < MM * 3; e += THREADS) cs[e] = coords[b * (MM * 3) + e];
    __syncthreads();

    float* __restrict__ dists  = out;
    float* __restrict__ angles = out + (size_t)MOL_B * MM * MM;

    // Zero-fill this CTA's contiguous angle slab (27 KB).
    {
        float4* zb = reinterpret_cast<float4*>(
            angles + (((size_t)b * MM + j0) * MM) * MM);
        const float4 z = make_float4(0.f, 0.f, 0.f, 0.f);
        #pragma unroll 8
        for (int e = tid; e < JS * MM * MM / 4; e += THREADS) zb[e] = z;
    }

    // Phase 1: warp r (<JS) handles row j0+r: distances, dists output, and
    // ballot-compacted neighbor vectors (v = r_q - r_j), d2, and index.
    if (wid < JS) {
        const int r = wid;
        const int p = j0 + r;
        const float px = cs[p * 3 + 0], py = cs[p * 3 + 1], pz = cs[p * 3 + 2];
        const unsigned below = (1u << lane) - 1u;

        // chunk 0: q = lane
        const int q0 = lane;
        float vx0 = cs[q0 * 3 + 0] - px;
        float vy0 = cs[q0 * 3 + 1] - py;
        float vz0 = cs[q0 * 3 + 2] - pz;
        float d20 = vx0 * vx0 + vy0 * vy0 + vz0 * vz0;
        float dist0 = sqrtf(d20);
        bool adj0 = (q0 != p) && (dist0 < CUTOFF_F);
        dists[((size_t)b * MM + p) * MM + q0] = adj0 ? dist0 : 0.0f;
        const unsigned m0 = __ballot_sync(0xffffffffu, adj0);

        // chunk 1: q = lane + 32 (lanes 0..15)
        bool adj1 = false;
        const int q1 = lane + 32;
        float vx1 = 0.f, vy1 = 0.f, vz1 = 0.f, d21 = 0.f;
        if (lane < 16) {
            vx1 = cs[q1 * 3 + 0] - px;
            vy1 = cs[q1 * 3 + 1] - py;
            vz1 = cs[q1 * 3 + 2] - pz;
            d21 = vx1 * vx1 + vy1 * vy1 + vz1 * vz1;
            float dist1 = sqrtf(d21);
            adj1 = (q1 != p) && (dist1 < CUTOFF_F);   // self-edge guard!
            dists[((size_t)b * MM + p) * MM + q1] = adj1 ? dist1 : 0.0f;
        }
        const unsigned m1 = __ballot_sync(0xffffffffu, adj1);

        const int c0 = __popc(m0);
        if (adj0) {
            const int s = __popc(m0 & below);
            nx[r][s] = vx0; ny[r][s] = vy0; nz[r][s] = vz0;
            nd2[r][s] = d20; nk[r][s] = q0;
        }
        if (adj1) {
            const int s = c0 + __popc(m1 & below);
            nx[r][s] = vx1; ny[r][s] = vy1; nz[r][s] = vz1;
            nd2[r][s] = d21; nk[r][s] = q1;
        }
        if (lane == 0) cnt[r] = c0 + __popc(m1);
    }
    __syncthreads();

    // Per-thread prefix over cnt[] (3 LDS broadcasts).
    const int c0 = cnt[0], c1 = cnt[1], c2 = cnt[2];
    const int o1 = c0 * c0;
    const int o2 = o1 + c1 * c1;
    const int total = o2 + c2 * c2;

    // Phase 3: compute + scatter only the real triplets (~375 per CTA).
    #pragma unroll 2
    for (int g = tid; g < total; g += THREADS) {
        const int jl = (g >= o1) + (g >= o2);
        const int p  = g - ((jl == 0) ? 0 : (jl == 1) ? o1 : o2);
        const int c  = (jl == 0) ? c0 : (jl == 1) ? c1 : c2;
        const int pi = (int)__fdividef((float)p + 0.5f, (float)c);
        const int ki = p - pi * c;

        const float vix = nx[jl][pi], viy = ny[jl][pi], viz = nz[jl][pi];
        const float vkx = nx[jl][ki], vky = ny[jl][ki], vkz = nz[jl][ki];
        const float a  = vix * vkx + viy * vky + viz * vkz;
        const float b2 = fmaxf(nd2[jl][pi] * nd2[jl][ki] - a * a, 0.f);
        const float ang = fast_atan2_pos(sqrtf(b2), a);

        if (pi != ki) {
            const int ii = nk[jl][pi];
            const int kk = nk[jl][ki];
            angles[(((size_t)b * MM + (j0 + jl)) * MM + ii) * MM + kk] = ang;
        }
    }
}

extern "C" void kernel_launch(void* const* d_in, const int* in_sizes, int n_in,
                              void* d_out, int out_size)
{
    const float* coords = (const float*)d_in[1];
    float* out = (float*)d_out;
    dimenet_kernel<<<MOL_B * SPLIT, THREADS>>>(coords, out);
}